// round 13
// baseline (speedup 1.0000x reference)
#include <cuda_runtime.h>
#include <cstdint>

// out[i] = W[inputs[i] - 1];  N = 16384*200 = 3,276,800;  W: 200 floats.
// Index dtype probe: idx_raw[1]==0 -> int64 (high word of elem 0), else int32.
//
// FINAL kernel. Best of 12 measured variants; all sane variants plateau at
// ~8.5 +/- 0.5us (run-to-run noise on identical SASS is +/-5%), which matches
// the platform floor for 39.3MB of mixed L2/DRAM traffic plus launch ramp:
//   - 800 CTAs x 512 thr, 1 unit/thread (unit = 8 out elems), exact cover
//   - ld.global.nc.L2::evict_last.v8.b32 index loads (pin the replay-reused
//     26.2MB index set in L2), st.global.L2::evict_first.v8.b32 output
//     stores (stream past L2, no dirty-eviction second pass)
//   - 32-way replicated W in smem: bank == lane, conflict-free gather
//   - index loads front-batched ahead of the W fill (latency overlap)

#define N_TOTAL   (16384 * 200)
#define MAX_RANKS 200
#define TPB       512
#define NBLK      (N_TOTAL / (TPB * 8))   // 800

struct V8 { uint32_t r0,r1,r2,r3,r4,r5,r6,r7; };

__device__ __forceinline__ V8 ldg_pin8(const void* p) {
    V8 v;
    asm volatile("ld.global.nc.L2::evict_last.v8.b32 "
                 "{%0,%1,%2,%3,%4,%5,%6,%7}, [%8];"
                 : "=r"(v.r0), "=r"(v.r1), "=r"(v.r2), "=r"(v.r3),
                   "=r"(v.r4), "=r"(v.r5), "=r"(v.r6), "=r"(v.r7)
                 : "l"(p));
    return v;
}

__device__ __forceinline__ void stg_stream8(void* p, const float* f) {
    asm volatile("st.global.L2::evict_first.v8.b32 "
                 "[%0], {%1,%2,%3,%4,%5,%6,%7,%8};"
                 :: "l"(p),
                    "f"(f[0]), "f"(f[1]), "f"(f[2]), "f"(f[3]),
                    "f"(f[4]), "f"(f[5]), "f"(f[6]), "f"(f[7])
                 : "memory");
}

__global__ __launch_bounds__(TPB)
void bias_gather_kernel(const uint32_t* __restrict__ idx_raw,
                        const float* __restrict__ W,
                        float* __restrict__ out)
{
    // 32-way replicated W: sW[rank*32 + lane] -> bank == lane, conflict-free.
    __shared__ float sW[MAX_RANKS * 32];

    const int tid  = threadIdx.x;
    const int lane = tid & 31;
    const int wid  = tid >> 5;

    // Unit = 8 output elements. Global unit id:
    const long long u = (long long)blockIdx.x * TPB + tid;   // < 409,600

    // ---- Front-batch all global index loads (overlap with W fill) ----
    const uint32_t probe = idx_raw[1];          // 0 => int64 indices
    const bool is64 = (probe == 0u);
    const char* ib = reinterpret_cast<const char*>(idx_raw);

    V8 a, b;
    if (is64) {
        a = ldg_pin8(ib + u * 64);       // 8 int64 idx: low words at even regs
        b = ldg_pin8(ib + u * 64 + 32);
    } else {
        a = ldg_pin8(ib + u * 32);       // 8 int32 idx
    }

    // ---- Fill replicated W while index loads are in flight ----
    #pragma unroll
    for (int k = wid; k < MAX_RANKS; k += TPB / 32) {
        float v = W[k];                  // warp-uniform addr: 1 sector
        sW[k * 32 + lane] = v;           // conflict-free STS
    }
    __syncthreads();

    // ---- Conflict-free gather + one streaming 256-bit store ----
    float r[8];
    if (is64) {
        r[0] = sW[((int)a.r0 - 1) * 32 + lane];
        r[1] = sW[((int)a.r2 - 1) * 32 + lane];
        r[2] = sW[((int)a.r4 - 1) * 32 + lane];
        r[3] = sW[((int)a.r6 - 1) * 32 + lane];
        r[4] = sW[((int)b.r0 - 1) * 32 + lane];
        r[5] = sW[((int)b.r2 - 1) * 32 + lane];
        r[6] = sW[((int)b.r4 - 1) * 32 + lane];
        r[7] = sW[((int)b.r6 - 1) * 32 + lane];
    } else {
        r[0] = sW[((int)a.r0 - 1) * 32 + lane];
        r[1] = sW[((int)a.r1 - 1) * 32 + lane];
        r[2] = sW[((int)a.r2 - 1) * 32 + lane];
        r[3] = sW[((int)a.r3 - 1) * 32 + lane];
        r[4] = sW[((int)a.r4 - 1) * 32 + lane];
        r[5] = sW[((int)a.r5 - 1) * 32 + lane];
        r[6] = sW[((int)a.r6 - 1) * 32 + lane];
        r[7] = sW[((int)a.r7 - 1) * 32 + lane];
    }

    stg_stream8(reinterpret_cast<char*>(out) + u * 32, r);
}

extern "C" void kernel_launch(void* const* d_in, const int* in_sizes, int n_in,
                              void* d_out, int out_size)
{
    const uint32_t* idx = (const uint32_t*)d_in[0];  // inputs [16384, 200]
    const float*    W   = (const float*)d_in[1];     // [200, 1]
    float*          out = (float*)d_out;

    bias_gather_kernel<<<NBLK, TPB>>>(idx, W, out);
}

// round 14
// speedup vs baseline: 1.0295x; 1.0295x over previous
#include <cuda_runtime.h>
#include <cstdint>

// out[i] = W[inputs[i] - 1];  N = 16384*200 = 3,276,800;  W: 200 floats.
// Probe idx_raw[1]: ==0 -> int64 indices, !=0 -> int32.
//
// Full bulk-DMA pipeline: BOTH index loads (cp.async.bulk g->s) and output
// stores (cp.async.bulk s->g) bypass the per-thread LDG/STG L1tex wavefront
// path. Per-thread work is smem-only: LDS idx, conflict-free replicated-sW
// gather, STS result. Double-buffered, 592 persistent CTAs x 512 thr.

#define N_TOTAL    (16384 * 200)
#define MAX_RANKS  200
#define TPB        512
#define NCTAS      592                      // 148 SMs * 4 CTAs
#define EPC        1024                     // elems per chunk (2/thread)
#define NCHUNKS    (N_TOTAL / EPC)          // 3200
#define OB_BYTES   (EPC * 4)                // 4096 out bytes per chunk

__device__ __forceinline__ uint32_t smem_u32(const void* p) {
    uint32_t a;
    asm("{ .reg .u64 t; cvta.to.shared.u64 t, %1; cvt.u32.u64 %0, t; }"
        : "=r"(a) : "l"(p));
    return a;
}
__device__ __forceinline__ void mbar_init(uint32_t m, uint32_t c) {
    asm volatile("mbarrier.init.shared.b64 [%0], %1;" :: "r"(m), "r"(c) : "memory");
}
__device__ __forceinline__ void bulk_load(uint32_t dst, const void* src,
                                          uint32_t bytes, uint32_t mbar) {
    asm volatile("mbarrier.arrive.expect_tx.shared::cta.b64 _, [%0], %1;"
                 :: "r"(mbar), "r"(bytes) : "memory");
    asm volatile("cp.async.bulk.shared::cta.global.mbarrier::complete_tx::bytes "
                 "[%0], [%1], %2, [%3];"
                 :: "r"(dst), "l"(src), "r"(bytes), "r"(mbar) : "memory");
}
__device__ __forceinline__ void bulk_store(void* gdst, uint32_t ssrc, uint32_t bytes) {
    asm volatile("cp.async.bulk.global.shared::cta.bulk_group [%0], [%1], %2;"
                 :: "l"(gdst), "r"(ssrc), "r"(bytes) : "memory");
}
__device__ __forceinline__ void mbar_wait(uint32_t m, uint32_t parity) {
    asm volatile(
        "{\n\t.reg .pred P;\n\t"
        "WL_%=:\n\t"
        "mbarrier.try_wait.parity.acquire.cta.shared::cta.b64 P, [%0], %1, 0x989680;\n\t"
        "@!P bra WL_%=;\n\t}"
        :: "r"(m), "r"(parity) : "memory");
}

__global__ __launch_bounds__(TPB)
void bias_gather_kernel(const uint32_t* __restrict__ idx_raw,
                        const float* __restrict__ W,
                        float* __restrict__ out)
{
    __shared__ float sW[MAX_RANKS * 32];                        // 25600 B
    __shared__ __align__(16) unsigned long long ibuf[2][EPC];   // 2 x 8192 B
    __shared__ __align__(16) float obuf[2][EPC];                // 2 x 4096 B
    __shared__ __align__(8)  unsigned long long mbar_s[2];

    const int tid  = threadIdx.x;
    const int lane = tid & 31;
    const int wid  = tid >> 5;
    const int bid  = blockIdx.x;

    const uint32_t probe = idx_raw[1];          // 0 => int64 indices
    const bool is64 = (probe == 0u);
    const uint32_t ic_bytes = is64 ? EPC * 8 : EPC * 4;

    const uint32_t mb[2] = { smem_u32(&mbar_s[0]), smem_u32(&mbar_s[1]) };
    const uint32_t ib[2] = { smem_u32(&ibuf[0][0]), smem_u32(&ibuf[1][0]) };
    const uint32_t ob[2] = { smem_u32(&obuf[0][0]), smem_u32(&obuf[1][0]) };

    if (tid == 0) { mbar_init(mb[0], 1); mbar_init(mb[1], 1); }
    __syncthreads();

    const char* gsrc = reinterpret_cast<const char*>(idx_raw);
    char*       gdst = reinterpret_cast<char*>(out);

    if (tid == 0) {
        long long c0 = bid;
        if (c0 < NCHUNKS) bulk_load(ib[0], gsrc + c0 * ic_bytes, ic_bytes, mb[0]);
        long long c1 = bid + NCTAS;
        if (c1 < NCHUNKS) bulk_load(ib[1], gsrc + c1 * ic_bytes, ic_bytes, mb[1]);
    }

    // Fill replicated W while the first DMAs fly (only non-bulk global loads).
    #pragma unroll
    for (int k = wid; k < MAX_RANKS; k += TPB / 32) {
        float v = W[k];                  // warp-uniform addr: 1 sector
        sW[k * 32 + lane] = v;           // conflict-free STS
    }
    __syncthreads();

    int k = 0;
    for (long long c = bid; c < NCHUNKS; c += NCTAS, k++) {
        const int      st     = k & 1;
        const uint32_t parity = (k >> 1) & 1;
        mbar_wait(mb[st], parity);

        // smem-only gather: 2 elems/thread, conflict-free LDS.
        float2 r;
        if (is64) {
            const ulonglong2 v =
                *reinterpret_cast<const ulonglong2*>(&ibuf[st][tid * 2]);
            r.x = sW[((int)v.x - 1) * 32 + lane];
            r.y = sW[((int)v.y - 1) * 32 + lane];
        } else {
            const uint2 v =
                *reinterpret_cast<const uint2*>(
                    reinterpret_cast<const char*>(&ibuf[st][0]) + tid * 8);
            r.x = sW[((int)v.x - 1) * 32 + lane];
            r.y = sW[((int)v.y - 1) * 32 + lane];
        }
        *reinterpret_cast<float2*>(&obuf[st][tid * 2]) = r;

        __syncthreads();   // obuf[st] complete; ibuf[st] fully consumed

        if (tid == 0) {
            // Order STS before async-proxy bulk read of obuf.
            asm volatile("fence.proxy.async.shared::cta;" ::: "memory");
            bulk_store(gdst + c * OB_BYTES, ob[st], OB_BYTES);
            asm volatile("cp.async.bulk.commit_group;" ::: "memory");
            // <=1 group still reading => store k-1 (and older) done:
            // obuf[st^1] is safe to overwrite next iteration.
            asm volatile("cp.async.bulk.wait_group.read 1;" ::: "memory");
            long long cn = c + 2 * NCTAS;
            if (cn < NCHUNKS)
                bulk_load(ib[st], gsrc + cn * ic_bytes, ic_bytes, mb[st]);
        }
        __syncthreads();   // broadcast store-completion / load-issue ordering
    }

    if (tid == 0)
        asm volatile("cp.async.bulk.wait_group.read 0;" ::: "memory");
}

extern "C" void kernel_launch(void* const* d_in, const int* in_sizes, int n_in,
                              void* d_out, int out_size)
{
    const uint32_t* idx = (const uint32_t*)d_in[0];  // inputs [16384, 200]
    const float*    W   = (const float*)d_in[1];     // [200, 1]
    float*          out = (float*)d_out;

    bias_gather_kernel<<<NCTAS, TPB>>>(idx, W, out);
}